// round 2
// baseline (speedup 1.0000x reference)
#include <cuda_runtime.h>
#include <cstdint>

#define B_ 4
#define S_ 2048
#define D_ 1024
#define H_ 16
#define DH_ 64
#define MROWS (B_ * S_)          // 8192
#define QKV_ELEMS (B_ * H_ * S_ * DH_)   // 8388608
#define C_ELEMS   (B_ * S_ * D_)         // 8388608

// -------- scratch (static device arrays; no allocation) --------
__device__ float g_q[QKV_ELEMS];
__device__ float g_k[QKV_ELEMS];
__device__ float g_v[QKV_ELEMS];
__device__ float g_c[C_ELEMS];

// -------- f32x2 packed helpers --------
__device__ __forceinline__ void fma2(unsigned long long &d, unsigned long long a, unsigned long long b) {
    asm("fma.rn.f32x2 %0, %1, %2, %3;" : "=l"(d) : "l"(a), "l"(b), "l"(d));
}
__device__ __forceinline__ void mul2(unsigned long long &d, unsigned long long a, unsigned long long b) {
    asm("mul.rn.f32x2 %0, %1, %2;" : "=l"(d) : "l"(a), "l"(b));
}
__device__ __forceinline__ unsigned long long bcast2(float x) {
    unsigned long long r;
    asm("mov.b64 %0, {%1, %2};" : "=l"(r) : "f"(x), "f"(x));
    return r;
}
__device__ __forceinline__ float lo2(unsigned long long v) {
    return __uint_as_float((unsigned)(v & 0xffffffffull));
}
__device__ __forceinline__ float hi2(unsigned long long v) {
    return __uint_as_float((unsigned)(v >> 32));
}

// ============================================================
// Kernel 1: fused per-head QKV projection. (unchanged from R1)
// ============================================================
__global__ __launch_bounds__(256) void qkv_proj_kernel(
    const float* __restrict__ x,
    const float* __restrict__ Wq,
    const float* __restrict__ Wk,
    const float* __restrict__ Wv)
{
    const int z = blockIdx.z;
    const float* W = (z == 0) ? Wq : ((z == 1) ? Wk : Wv);
    float* out = (z == 0) ? g_q : ((z == 1) ? g_k : g_v);
    const float scale = (z == 0) ? 0.125f : 1.0f;

    const int h  = blockIdx.y;
    const int m0 = blockIdx.x * 128;

    __shared__ float Xs[16][136];   // transposed: Xs[k][m]
    __shared__ float Ws[16][72];    // Ws[k][n]

    const int tid = threadIdx.x;
    const int tyr = tid >> 4;
    const int txc = tid & 15;

    unsigned long long acc[4][4];
    #pragma unroll
    for (int p = 0; p < 4; ++p)
        #pragma unroll
        for (int c = 0; c < 4; ++c) acc[p][c] = 0ull;

    const float* Wh = W + (size_t)h * D_ * DH_;

    for (int kt = 0; kt < D_ / 16; ++kt) {
        const int k0 = kt * 16;
        #pragma unroll
        for (int it = 0; it < 2; ++it) {
            int f  = tid + it * 256;
            int r  = f >> 2;
            int c4 = f & 3;
            float4 v = *(const float4*)(x + (size_t)(m0 + r) * D_ + k0 + c4 * 4);
            Xs[c4 * 4 + 0][r] = v.x;
            Xs[c4 * 4 + 1][r] = v.y;
            Xs[c4 * 4 + 2][r] = v.z;
            Xs[c4 * 4 + 3][r] = v.w;
        }
        {
            int r  = tid >> 4;
            int e4 = tid & 15;
            float4 v = *(const float4*)(Wh + (size_t)(k0 + r) * DH_ + e4 * 4);
            *(float4*)&Ws[r][e4 * 4] = v;
        }
        __syncthreads();

        #pragma unroll
        for (int k = 0; k < 16; ++k) {
            unsigned long long a2[4];
            #pragma unroll
            for (int p = 0; p < 4; ++p)
                a2[p] = *(const unsigned long long*)&Xs[k][tyr * 8 + 2 * p];
            unsigned long long b2[4];
            #pragma unroll
            for (int c = 0; c < 4; ++c)
                b2[c] = bcast2(Ws[k][txc * 4 + c]);
            #pragma unroll
            for (int p = 0; p < 4; ++p)
                #pragma unroll
                for (int c = 0; c < 4; ++c)
                    fma2(acc[p][c], a2[p], b2[c]);
        }
        __syncthreads();
    }

    #pragma unroll
    for (int p = 0; p < 4; ++p) {
        int rlo = m0 + tyr * 8 + 2 * p;
        int rhi = rlo + 1;
        float4 vlo, vhi;
        vlo.x = lo2(acc[p][0]) * scale; vlo.y = lo2(acc[p][1]) * scale;
        vlo.z = lo2(acc[p][2]) * scale; vlo.w = lo2(acc[p][3]) * scale;
        vhi.x = hi2(acc[p][0]) * scale; vhi.y = hi2(acc[p][1]) * scale;
        vhi.z = hi2(acc[p][2]) * scale; vhi.w = hi2(acc[p][3]) * scale;
        {
            int b = rlo >> 11, s = rlo & 2047;
            *(float4*)(out + (((size_t)(b * H_ + h) * S_ + s) * DH_) + txc * 4) = vlo;
        }
        {
            int b = rhi >> 11, s = rhi & 2047;
            *(float4*)(out + (((size_t)(b * H_ + h) * S_ + s) * DH_) + txc * 4) = vhi;
        }
    }
}

// ============================================================
// Kernel 2: causal flash attention, fp32, f32x2-packed math.
// One block = 64 query rows of one (b,h). 128 threads.
// Thread: rows (rp, rp+32), score cols c = q4+4j, out cols e = q4*16..+15.
// QK^T: accumulate even/odd-e partial sums in one f32x2 (no ALU packing).
// PV:   pack over e-pairs (V contiguous in e), p broadcast per (row,c).
// ============================================================
#define LDT 68
#define ATTN_SMEM (4 * 64 * LDT * 4)

__global__ __launch_bounds__(128) void attn_kernel()
{
    extern __shared__ float sm[];
    float* Qs = sm;
    float* Ks = sm + 64 * LDT;
    float* Vs = sm + 2 * 64 * LDT;
    float* Ps = sm + 3 * 64 * LDT;

    const int tid = threadIdx.x;
    const int rp  = tid >> 2;   // 0..31
    const int q4  = tid & 3;    // 0..3
    const int rA  = rp;
    const int rB  = rp + 32;

    const int bh = blockIdx.y;
    const int qt = (gridDim.x - 1) - blockIdx.x;  // big tiles first

    // load Q tile (64x64)
    const float* qg = g_q + ((size_t)bh * S_ + qt * 64) * DH_;
    for (int idx = tid; idx < 1024; idx += 128) {
        int row = idx >> 4, c4 = idx & 15;
        float4 v = *(const float4*)(qg + (size_t)row * DH_ + c4 * 4);
        *(float4*)&Qs[row * LDT + c4 * 4] = v;
    }

    float mA = -3.0e38f, mB = -3.0e38f;
    float lA = 0.f, lB = 0.f;
    unsigned long long o2A[8], o2B[8];   // packed over e-pairs
    #pragma unroll
    for (int i = 0; i < 8; ++i) { o2A[i] = 0ull; o2B[i] = 0ull; }

    for (int kt = 0; kt <= qt; ++kt) {
        __syncthreads();  // prev PV / Q load done before overwriting K,V
        const float* kg = g_k + ((size_t)bh * S_ + kt * 64) * DH_;
        const float* vg = g_v + ((size_t)bh * S_ + kt * 64) * DH_;
        for (int idx = tid; idx < 1024; idx += 128) {
            int row = idx >> 4, c4 = idx & 15;
            float4 kv = *(const float4*)(kg + (size_t)row * DH_ + c4 * 4);
            *(float4*)&Ks[row * LDT + c4 * 4] = kv;
            float4 vv = *(const float4*)(vg + (size_t)row * DH_ + c4 * 4);
            *(float4*)&Vs[row * LDT + c4 * 4] = vv;
        }
        __syncthreads();

        // ---- scores: f32x2 partial sums over even/odd e ----
        unsigned long long a2A[16], a2B[16];
        #pragma unroll
        for (int j = 0; j < 16; ++j) { a2A[j] = 0ull; a2B[j] = 0ull; }

        #pragma unroll 2
        for (int e0 = 0; e0 < 64; e0 += 4) {
            ulonglong2 qa = *(const ulonglong2*)&Qs[rA * LDT + e0];
            ulonglong2 qb = *(const ulonglong2*)&Qs[rB * LDT + e0];
            #pragma unroll
            for (int j = 0; j < 16; ++j) {
                ulonglong2 kk = *(const ulonglong2*)&Ks[(q4 + 4 * j) * LDT + e0];
                fma2(a2A[j], qa.x, kk.x);
                fma2(a2A[j], qa.y, kk.y);
                fma2(a2B[j], qb.x, kk.x);
                fma2(a2B[j], qb.y, kk.y);
            }
        }

        float sA[16], sB[16];
        #pragma unroll
        for (int j = 0; j < 16; ++j) {
            sA[j] = lo2(a2A[j]) + hi2(a2A[j]);
            sB[j] = lo2(a2B[j]) + hi2(a2B[j]);
        }

        if (kt == qt) {  // causal mask inside diagonal tile
            #pragma unroll
            for (int j = 0; j < 16; ++j) {
                int c = q4 + 4 * j;
                if (c > rA) sA[j] = -3.0e38f;
                if (c > rB) sB[j] = -3.0e38f;
            }
        }

        // ---- online softmax (rows owned by 4-thread quads) ----
        float mtA = -3.0e38f, mtB = -3.0e38f;
        #pragma unroll
        for (int j = 0; j < 16; ++j) { mtA = fmaxf(mtA, sA[j]); mtB = fmaxf(mtB, sB[j]); }
        mtA = fmaxf(mtA, __shfl_xor_sync(0xffffffffu, mtA, 1));
        mtA = fmaxf(mtA, __shfl_xor_sync(0xffffffffu, mtA, 2));
        mtB = fmaxf(mtB, __shfl_xor_sync(0xffffffffu, mtB, 1));
        mtB = fmaxf(mtB, __shfl_xor_sync(0xffffffffu, mtB, 2));

        float mnA = fmaxf(mA, mtA);
        float mnB = fmaxf(mB, mtB);
        float corrA = __expf(mA - mnA);
        float corrB = __expf(mB - mnB);

        float rsA = 0.f, rsB = 0.f;
        #pragma unroll
        for (int j = 0; j < 16; ++j) {
            float pa = __expf(sA[j] - mnA); sA[j] = pa; rsA += pa;
            float pb = __expf(sB[j] - mnB); sB[j] = pb; rsB += pb;
        }
        rsA += __shfl_xor_sync(0xffffffffu, rsA, 1);
        rsA += __shfl_xor_sync(0xffffffffu, rsA, 2);
        rsB += __shfl_xor_sync(0xffffffffu, rsB, 1);
        rsB += __shfl_xor_sync(0xffffffffu, rsB, 2);

        lA = lA * corrA + rsA;
        lB = lB * corrB + rsB;
        {
            unsigned long long cA2 = bcast2(corrA);
            unsigned long long cB2 = bcast2(corrB);
            #pragma unroll
            for (int i = 0; i < 8; ++i) { mul2(o2A[i], o2A[i], cA2); mul2(o2B[i], o2B[i], cB2); }
        }
        mA = mnA; mB = mnB;

        #pragma unroll
        for (int j = 0; j < 16; ++j) {
            int c = q4 + 4 * j;
            Ps[rA * LDT + c] = sA[j];
            Ps[rB * LDT + c] = sB[j];
        }
        __syncthreads();

        // ---- O += P V, packed over e-pairs ----
        #pragma unroll 4
        for (int c = 0; c < 64; ++c) {
            unsigned long long pa2 = bcast2(Ps[rA * LDT + c]);
            unsigned long long pb2 = bcast2(Ps[rB * LDT + c]);
            const ulonglong2* vp = (const ulonglong2*)&Vs[c * LDT + q4 * 16];
            #pragma unroll
            for (int ii = 0; ii < 4; ++ii) {
                ulonglong2 vv = vp[ii];
                fma2(o2A[2 * ii + 0], pa2, vv.x);
                fma2(o2A[2 * ii + 1], pa2, vv.y);
                fma2(o2B[2 * ii + 0], pb2, vv.x);
                fma2(o2B[2 * ii + 1], pb2, vv.y);
            }
        }
    }

    // finalize: concat layout g_c[b, s, h*DH + e]
    const unsigned long long invA2 = bcast2(1.0f / lA);
    const unsigned long long invB2 = bcast2(1.0f / lB);
    const int b = bh >> 4, h = bh & 15;
    unsigned long long* cA = (unsigned long long*)(g_c + ((size_t)b * S_ + (qt * 64 + rA)) * D_ + h * DH_ + q4 * 16);
    unsigned long long* cB = (unsigned long long*)(g_c + ((size_t)b * S_ + (qt * 64 + rB)) * D_ + h * DH_ + q4 * 16);
    #pragma unroll
    for (int i = 0; i < 8; ++i) {
        unsigned long long wa, wb;
        mul2(wa, o2A[i], invA2);
        mul2(wb, o2B[i], invB2);
        cA[i] = wa;
        cB[i] = wb;
    }
}

// ============================================================
// Kernel 3: output projection out = concat @ Wo + bo (unchanged)
// ============================================================
__global__ __launch_bounds__(256) void out_proj_kernel(
    const float* __restrict__ Wo,
    const float* __restrict__ bo,
    float* __restrict__ out)
{
    const int n0 = blockIdx.y * 64;
    const int m0 = blockIdx.x * 128;

    __shared__ float Xs[16][136];
    __shared__ float Ws[16][72];

    const int tid = threadIdx.x;
    const int tyr = tid >> 4;
    const int txc = tid & 15;

    unsigned long long acc[4][4];
    #pragma unroll
    for (int p = 0; p < 4; ++p)
        #pragma unroll
        for (int c = 0; c < 4; ++c) acc[p][c] = 0ull;

    for (int kt = 0; kt < D_ / 16; ++kt) {
        const int k0 = kt * 16;
        #pragma unroll
        for (int it = 0; it < 2; ++it) {
            int f  = tid + it * 256;
            int r  = f >> 2;
            int c4 = f & 3;
            float4 v = *(const float4*)(g_c + (size_t)(m0 + r) * D_ + k0 + c4 * 4);
            Xs[c4 * 4 + 0][r] = v.x;
            Xs[c4 * 4 + 1][r] = v.y;
            Xs[c4 * 4 + 2][r] = v.z;
            Xs[c4 * 4 + 3][r] = v.w;
        }
        {
            int r  = tid >> 4;
            int e4 = tid & 15;
            float4 v = *(const float4*)(Wo + (size_t)(k0 + r) * D_ + n0 + e4 * 4);
            *(float4*)&Ws[r][e4 * 4] = v;
        }
        __syncthreads();

        #pragma unroll
        for (int k = 0; k < 16; ++k) {
            unsigned long long a2[4];
            #pragma unroll
            for (int p = 0; p < 4; ++p)
                a2[p] = *(const unsigned long long*)&Xs[k][tyr * 8 + 2 * p];
            unsigned long long b2[4];
            #pragma unroll
            for (int c = 0; c < 4; ++c)
                b2[c] = bcast2(Ws[k][txc * 4 + c]);
            #pragma unroll
            for (int p = 0; p < 4; ++p)
                #pragma unroll
                for (int c = 0; c < 4; ++c)
                    fma2(acc[p][c], a2[p], b2[c]);
        }
        __syncthreads();
    }

    float4 bias = *(const float4*)(bo + n0 + txc * 4);
    #pragma unroll
    for (int p = 0; p < 4; ++p) {
        int rlo = m0 + tyr * 8 + 2 * p;
        int rhi = rlo + 1;
        float4 vlo, vhi;
        vlo.x = lo2(acc[p][0]) + bias.x; vlo.y = lo2(acc[p][1]) + bias.y;
        vlo.z = lo2(acc[p][2]) + bias.z; vlo.w = lo2(acc[p][3]) + bias.w;
        vhi.x = hi2(acc[p][0]) + bias.x; vhi.y = hi2(acc[p][1]) + bias.y;
        vhi.z = hi2(acc[p][2]) + bias.z; vhi.w = hi2(acc[p][3]) + bias.w;
        *(float4*)(out + (size_t)rlo * D_ + n0 + txc * 4) = vlo;
        *(float4*)(out + (size_t)rhi * D_ + n0 + txc * 4) = vhi;
    }
}

// ============================================================
extern "C" void kernel_launch(void* const* d_in, const int* in_sizes, int n_in,
                              void* d_out, int out_size)
{
    const float* x  = (const float*)d_in[0];
    const float* Wq = (const float*)d_in[1];
    const float* Wk = (const float*)d_in[2];
    const float* Wv = (const float*)d_in[3];
    const float* Wo = (const float*)d_in[4];
    const float* bo = (const float*)d_in[5];
    float* out = (float*)d_out;

    cudaFuncSetAttribute(attn_kernel, cudaFuncAttributeMaxDynamicSharedMemorySize, ATTN_SMEM);

    qkv_proj_kernel<<<dim3(MROWS / 128, H_, 3), 256>>>(x, Wq, Wk, Wv);
    attn_kernel<<<dim3(S_ / 64, B_ * H_), 128, ATTN_SMEM>>>();
    out_proj_kernel<<<dim3(MROWS / 128, D_ / 64), 256>>>(Wo, bo, out);
}

// round 4
// speedup vs baseline: 1.2532x; 1.2532x over previous
#include <cuda_runtime.h>
#include <cuda_bf16.h>
#include <cstdint>

#define B_ 4
#define S_ 2048
#define D_ 1024
#define H_ 16
#define DH_ 64
#define MROWS (B_ * S_)
#define QKV_ELEMS (B_ * H_ * S_ * DH_)
#define C_ELEMS   (B_ * S_ * D_)

__device__ float g_q[QKV_ELEMS];
__device__ float g_k[QKV_ELEMS];
__device__ float g_v[QKV_ELEMS];
__device__ float g_c[C_ELEMS];

// ================= helpers =================
__device__ __forceinline__ uint32_t smem_u32(const void* p) {
    uint32_t a;
    asm("{ .reg .u64 t; cvta.to.shared.u64 t, %1; cvt.u32.u64 %0, t; }" : "=r"(a) : "l"(p));
    return a;
}
// bf16 hi/lo split
__device__ __forceinline__ void bsplit(float v, float& h, float& l) {
    __nv_bfloat16 bh = __float2bfloat16(v);
    h = __bfloat162float(bh);
    l = v - h;
}
// pack two floats into bf16x2 (lo_elem -> low half / lower address)
__device__ __forceinline__ uint32_t packbf(float lo_elem, float hi_elem) {
    uint32_t r;
    asm("cvt.rn.bf16x2.f32 %0, %1, %2;" : "=r"(r) : "f"(hi_elem), "f"(lo_elem));
    return r;
}
#define LDSM_X4(r0, r1, r2, r3, addr) \
    asm volatile("ldmatrix.sync.aligned.m8n8.x4.shared.b16 {%0,%1,%2,%3}, [%4];" \
        : "=r"(r0), "=r"(r1), "=r"(r2), "=r"(r3) : "r"(addr))

__device__ __forceinline__ void mma16816(float* c,
    uint32_t a0, uint32_t a1, uint32_t a2, uint32_t a3, uint32_t b0, uint32_t b1)
{
    asm volatile(
        "mma.sync.aligned.m16n8k16.row.col.f32.bf16.bf16.f32 "
        "{%0,%1,%2,%3}, {%4,%5,%6,%7}, {%8,%9}, {%0,%1,%2,%3};"
        : "+f"(c[0]), "+f"(c[1]), "+f"(c[2]), "+f"(c[3])
        : "r"(a0), "r"(a1), "r"(a2), "r"(a3), "r"(b0), "r"(b1));
}

// f32x2 helpers (attention)
__device__ __forceinline__ void fma2(unsigned long long &d, unsigned long long a, unsigned long long b) {
    asm("fma.rn.f32x2 %0, %1, %2, %3;" : "=l"(d) : "l"(a), "l"(b), "l"(d));
}
__device__ __forceinline__ void mul2(unsigned long long &d, unsigned long long a, unsigned long long b) {
    asm("mul.rn.f32x2 %0, %1, %2;" : "=l"(d) : "l"(a), "l"(b));
}
__device__ __forceinline__ unsigned long long bcast2(float x) {
    unsigned long long r;
    asm("mov.b64 %0, {%1, %2};" : "=l"(r) : "f"(x), "f"(x));
    return r;
}
__device__ __forceinline__ float lo2(unsigned long long v) { return __uint_as_float((unsigned)(v & 0xffffffffull)); }
__device__ __forceinline__ float hi2(unsigned long long v) { return __uint_as_float((unsigned)(v >> 32)); }

// ============================================================
// mma.sync bf16 split-3 GEMM config: CTA tile 128x128, BK=32.
// smem tiles: [128 rows][40 halves] (80B stride: 16B aligned,
// ldmatrix conflict-free since 5r mod 8 is a permutation).
// 8 warps: warp_m = wid&1 (2 x 64 rows), warp_n = wid>>1 (4 x 32 cols).
// ============================================================
#define SROW 20   // words per smem row (40 halves = 80B)
#define NKT (D_ / 32)

struct MmaTiles {
    uint32_t Ah[128 * SROW];
    uint32_t Al[128 * SROW];
    uint32_t Bh[128 * SROW];
    uint32_t Bl[128 * SROW];
};

// ---- shared inner machinery (A load + mma phase) ----
// A: 128x32 floats from src (row stride ld), split into Ah/Al.
__device__ __forceinline__ void load_a_tile(MmaTiles* t, const float* src, int ld, int k0, int m0, int tid)
{
    #pragma unroll
    for (int i = 0; i < 4; ++i) {
        int idx = tid + i * 256;
        int r = idx >> 3, c4 = idx & 7;
        float4 v = *(const float4*)(src + (size_t)(m0 + r) * ld + k0 + c4 * 4);
        float hx, lx, hy, ly, hz, lz, hw, lw;
        bsplit(v.x, hx, lx); bsplit(v.y, hy, ly);
        bsplit(v.z, hz, lz); bsplit(v.w, hw, lw);
        int w = r * SROW + c4 * 2;
        t->Ah[w]     = packbf(hx, hy);
        t->Ah[w + 1] = packbf(hz, hw);
        t->Al[w]     = packbf(lx, ly);
        t->Al[w + 1] = packbf(lz, lw);
    }
}

// mma phase over one BK=32 tile; acc[i][j][4]
__device__ __forceinline__ void mma_phase(MmaTiles* t, float acc[4][4][4], int wid, int lane)
{
    const int warp_m = wid & 1;
    const int warp_n = wid >> 1;
    const uint32_t base = smem_u32(t);
    const uint32_t a_hi_b = base;
    const uint32_t a_lo_b = base + 128 * SROW * 4;
    const uint32_t b_hi_b = base + 2 * 128 * SROW * 4;
    const uint32_t b_lo_b = base + 3 * 128 * SROW * 4;

    // lane offsets (halves)
    const int a_row = warp_m * 64 + (lane & 15);
    const int a_kh  = (lane >> 4) << 3;
    const int b_row = warp_n * 32 + (lane & 7) + ((lane >> 4) << 3);
    const int b_kh  = ((lane >> 3) & 1) << 3;

    #pragma unroll
    for (int ks = 0; ks < 2; ++ks) {
        const int koff = ks * 16;
        uint32_t ah[4][4], bh[2][4], bl[2][4];
        #pragma unroll
        for (int i = 0; i < 4; ++i) {
            uint32_t addr = a_hi_b + ((a_row + i * 16) * 40 + koff + a_kh) * 2;
            LDSM_X4(ah[i][0], ah[i][1], ah[i][2], ah[i][3], addr);
        }
        #pragma unroll
        for (int jj = 0; jj < 2; ++jj) {
            uint32_t addr = b_hi_b + ((b_row + jj * 16) * 40 + koff + b_kh) * 2;
            LDSM_X4(bh[jj][0], bh[jj][1], bh[jj][2], bh[jj][3], addr);
            uint32_t addr2 = b_lo_b + ((b_row + jj * 16) * 40 + koff + b_kh) * 2;
            LDSM_X4(bl[jj][0], bl[jj][1], bl[jj][2], bl[jj][3], addr2);
        }
        // hh + hl
        #pragma unroll
        for (int i = 0; i < 4; ++i)
            #pragma unroll
            for (int j = 0; j < 4; ++j) {
                int jj = j >> 1, s = (j & 1) * 2;
                mma16816(acc[i][j], ah[i][0], ah[i][1], ah[i][2], ah[i][3], bh[jj][s], bh[jj][s + 1]);
                mma16816(acc[i][j], ah[i][0], ah[i][1], ah[i][2], ah[i][3], bl[jj][s], bl[jj][s + 1]);
            }
        // lh (reload A-lo into the same regs)
        #pragma unroll
        for (int i = 0; i < 4; ++i) {
            uint32_t addr = a_lo_b + ((a_row + i * 16) * 40 + koff + a_kh) * 2;
            LDSM_X4(ah[i][0], ah[i][1], ah[i][2], ah[i][3], addr);
        }
        #pragma unroll
        for (int i = 0; i < 4; ++i)
            #pragma unroll
            for (int j = 0; j < 4; ++j) {
                int jj = j >> 1, s = (j & 1) * 2;
                mma16816(acc[i][j], ah[i][0], ah[i][1], ah[i][2], ah[i][3], bh[jj][s], bh[jj][s + 1]);
            }
    }
}

// ============================================================
// Kernel 1: QKV projection. grid = (64, 8, 3), block 256.
// N=128 = 2 heads x 64. B tile rows: n = head_sel*64 + e.
// ============================================================
__global__ __launch_bounds__(256, 1) void qkv_mma_kernel(
    const float* __restrict__ x,
    const float* __restrict__ Wq,
    const float* __restrict__ Wk,
    const float* __restrict__ Wv)
{
    __shared__ MmaTiles t;
    const int tid = threadIdx.x;
    const int wid = tid >> 5;
    const int lane = tid & 31;

    const int z = blockIdx.z;
    const float* W = (z == 0) ? Wq : ((z == 1) ? Wk : Wv);
    float* outp = (z == 0) ? g_q : ((z == 1) ? g_k : g_v);
    const float scale = (z == 0) ? 0.125f : 1.0f;
    const int hp = blockIdx.y;
    const int m0 = blockIdx.x * 128;

    float acc[4][4][4];
    #pragma unroll
    for (int i = 0; i < 4; ++i)
        #pragma unroll
        for (int j = 0; j < 4; ++j)
            #pragma unroll
            for (int q = 0; q < 4; ++q) acc[i][j][q] = 0.f;

    // B-load indexing
    const int e_loc = tid & 127;
    const int kc = tid >> 7;             // 0..1 -> k 0..15 / 16..31
    const int head = hp * 2 + (e_loc >> 6);
    const int e = e_loc & 63;
    const float* wcol = W + (size_t)head * (D_ * DH_) + e;

    for (int kt = 0; kt < NKT; ++kt) {
        const int k0 = kt * 32;
        if (kt) __syncthreads();

        load_a_tile(&t, x, D_, k0, m0, tid);

        #pragma unroll
        for (int i = 0; i < 16; i += 2) {
            int k = kc * 16 + i;
            float v0 = wcol[(size_t)(k0 + k) * DH_];
            float v1 = wcol[(size_t)(k0 + k + 1) * DH_];
            float h0, l0, h1, l1;
            bsplit(v0, h0, l0); bsplit(v1, h1, l1);
            int w = e_loc * SROW + k / 2;
            t.Bh[w] = packbf(h0, h1);
            t.Bl[w] = packbf(l0, l1);
        }
        __syncthreads();

        mma_phase(&t, acc, wid, lane);
    }

    // epilogue
    const int warp_m = wid & 1;
    const int warp_n = wid >> 1;
    #pragma unroll
    for (int i = 0; i < 4; ++i) {
        #pragma unroll
        for (int j = 0; j < 4; ++j) {
            int r0 = m0 + warp_m * 64 + i * 16 + (lane >> 2);
            int col = warp_n * 32 + j * 8 + (lane & 3) * 2;
            int hh = hp * 2 + (col >> 6);
            int ee = col & 63;
            {
                int b = r0 >> 11, s = r0 & 2047;
                float2 v; v.x = acc[i][j][0] * scale; v.y = acc[i][j][1] * scale;
                *(float2*)(outp + (((size_t)(b * H_ + hh) * S_ + s) * DH_) + ee) = v;
            }
            {
                int r1 = r0 + 8;
                int b = r1 >> 11, s = r1 & 2047;
                float2 v; v.x = acc[i][j][2] * scale; v.y = acc[i][j][3] * scale;
                *(float2*)(outp + (((size_t)(b * H_ + hh) * S_ + s) * DH_) + ee) = v;
            }
        }
    }
}

// ============================================================
// Kernel 3: output projection. grid = (64, 8), block 256.
// ============================================================
__global__ __launch_bounds__(256, 1) void out_proj_mma_kernel(
    const float* __restrict__ Wo,
    const float* __restrict__ bo,
    float* __restrict__ out)
{
    __shared__ MmaTiles t;
    const int tid = threadIdx.x;
    const int wid = tid >> 5;
    const int lane = tid & 31;

    const int n0 = blockIdx.y * 128;
    const int m0 = blockIdx.x * 128;

    float acc[4][4][4];
    #pragma unroll
    for (int i = 0; i < 4; ++i)
        #pragma unroll
        for (int j = 0; j < 4; ++j)
            #pragma unroll
            for (int q = 0; q < 4; ++q) acc[i][j][q] = 0.f;

    const int e_loc = tid & 127;
    const int kc = tid >> 7;
    const float* wcol = Wo + n0 + e_loc;

    for (int kt = 0; kt < NKT; ++kt) {
        const int k0 = kt * 32;
        if (kt) __syncthreads();

        load_a_tile(&t, g_c, D_, k0, m0, tid);

        #pragma unroll
        for (int i = 0; i < 16; i += 2) {
            int k = kc * 16 + i;
            float v0 = wcol[(size_t)(k0 + k) * D_];
            float v1 = wcol[(size_t)(k0 + k + 1) * D_];
            float h0, l0, h1, l1;
            bsplit(v0, h0, l0); bsplit(v1, h1, l1);
            int w = e_loc * SROW + k / 2;
            t.Bh[w] = packbf(h0, h1);
            t.Bl[w] = packbf(l0, l1);
        }
        __syncthreads();

        mma_phase(&t, acc, wid, lane);
    }

    const int warp_m = wid & 1;
    const int warp_n = wid >> 1;
    #pragma unroll
    for (int i = 0; i < 4; ++i) {
        #pragma unroll
        for (int j = 0; j < 4; ++j) {
            int r0 = m0 + warp_m * 64 + i * 16 + (lane >> 2);
            int col = n0 + warp_n * 32 + j * 8 + (lane & 3) * 2;
            float b0 = bo[col], b1 = bo[col + 1];
            {
                float2 v; v.x = acc[i][j][0] + b0; v.y = acc[i][j][1] + b1;
                *(float2*)(out + (size_t)r0 * D_ + col) = v;
            }
            {
                float2 v; v.x = acc[i][j][2] + b0; v.y = acc[i][j][3] + b1;
                *(float2*)(out + (size_t)(r0 + 8) * D_ + col) = v;
            }
        }
    }
}

// ============================================================
// Kernel 2: causal flash attention, fp32, f32x2-packed (R2, proven)
// ============================================================
#define LDT 68
#define ATTN_SMEM (4 * 64 * LDT * 4)

__global__ __launch_bounds__(128) void attn_kernel()
{
    extern __shared__ float smf[];
    float* Qs = smf;
    float* Ks = smf + 64 * LDT;
    float* Vs = smf + 2 * 64 * LDT;
    float* Ps = smf + 3 * 64 * LDT;

    const int tid = threadIdx.x;
    const int rp  = tid >> 2;
    const int q4  = tid & 3;
    const int rA  = rp;
    const int rB  = rp + 32;

    const int bh = blockIdx.y;
    const int qt = (gridDim.x - 1) - blockIdx.x;

    const float* qg = g_q + ((size_t)bh * S_ + qt * 64) * DH_;
    for (int idx = tid; idx < 1024; idx += 128) {
        int row = idx >> 4, c4 = idx & 15;
        float4 v = *(const float4*)(qg + (size_t)row * DH_ + c4 * 4);
        *(float4*)&Qs[row * LDT + c4 * 4] = v;
    }

    float mA = -3.0e38f, mB = -3.0e38f;
    float lA = 0.f, lB = 0.f;
    unsigned long long o2A[8], o2B[8];
    #pragma unroll
    for (int i = 0; i < 8; ++i) { o2A[i] = 0ull; o2B[i] = 0ull; }

    for (int kt = 0; kt <= qt; ++kt) {
        __syncthreads();
        const float* kg = g_k + ((size_t)bh * S_ + kt * 64) * DH_;
        const float* vg = g_v + ((size_t)bh * S_ + kt * 64) * DH_;
        for (int idx = tid; idx < 1024; idx += 128) {
            int row = idx >> 4, c4 = idx & 15;
            float4 kv = *(const float4*)(kg + (size_t)row * DH_ + c4 * 4);
            *(float4*)&Ks[row * LDT + c4 * 4] = kv;
            float4 vv = *(const float4*)(vg + (size_t)row * DH_ + c4 * 4);
            *(float4*)&Vs[row * LDT + c4 * 4] = vv;
        }
        __syncthreads();

        unsigned long long a2A[16], a2B[16];
        #pragma unroll
        for (int j = 0; j < 16; ++j) { a2A[j] = 0ull; a2B[j] = 0ull; }

        #pragma unroll 2
        for (int e0 = 0; e0 < 64; e0 += 4) {
            ulonglong2 qa = *(const ulonglong2*)&Qs[rA * LDT + e0];
            ulonglong2 qb = *(const ulonglong2*)&Qs[rB * LDT + e0];
            #pragma unroll
            for (int j = 0; j < 16; ++j) {
                ulonglong2 kk = *(const ulonglong2*)&Ks[(q4 + 4 * j) * LDT + e0];
                fma2(a2A[j], qa.x, kk.x);
                fma2(a2A[j], qa.y, kk.y);
                fma2(a2B[j], qb.x, kk.x);
                fma2(a2B[j], qb.y, kk.y);
            }
        }

        float sA[16], sB[16];
        #pragma unroll
        for (int j = 0; j < 16; ++j) {
            sA[j] = lo2(a2A[j]) + hi2(a2A[j]);
            sB[j] = lo2(a2B[j]) + hi2(a2B[j]);
        }

        if (kt == qt) {
            #pragma unroll
            for (int j = 0; j < 16; ++j) {
                int c = q4 + 4 * j;
                if (c > rA) sA[j] = -3.0e38f;
                if (c > rB) sB[j] = -3.0e38f;
            }
        }

        float mtA = -3.0e38f, mtB = -3.0e38f;
        #pragma unroll
        for (int j = 0; j < 16; ++j) { mtA = fmaxf(mtA, sA[j]); mtB = fmaxf(mtB, sB[j]); }
        mtA = fmaxf(mtA, __shfl_xor_sync(0xffffffffu, mtA, 1));
        mtA = fmaxf(mtA, __shfl_xor_sync(0xffffffffu, mtA, 2));
        mtB = fmaxf(mtB, __shfl_xor_sync(0xffffffffu, mtB, 1));
        mtB = fmaxf(mtB, __shfl_xor_sync(0xffffffffu, mtB, 2));

        float mnA = fmaxf(mA, mtA);
        float mnB = fmaxf(mB, mtB);
        float corrA = __expf(mA - mnA);
        float corrB = __expf(mB - mnB);

        float rsA = 0.f, rsB = 0.f;
        #pragma unroll
        for (int j = 0; j < 16; ++j) {
            float pa = __expf(sA[j] - mnA); sA[j] = pa; rsA += pa;
            float pb = __expf(sB[j] - mnB); sB[j] = pb; rsB += pb;
        }
        rsA += __shfl_xor_sync(0xffffffffu, rsA, 1);
        rsA += __shfl_xor_sync(0xffffffffu, rsA, 2);
        rsB += __shfl_xor_sync(0xffffffffu, rsB, 1);
        rsB += __shfl_xor_sync(0xffffffffu, rsB, 2);

        lA = lA * corrA + rsA;
        lB = lB * corrB + rsB;
        {
            unsigned long long cA2 = bcast2(corrA);
            unsigned long long cB2 = bcast2(corrB);
            #pragma unroll
            for (int i = 0; i < 8; ++i) { mul2(o2A[i], o2A[i], cA2); mul2(o2B[i], o2B[i], cB2); }
        }
        mA = mnA; mB = mnB;

        #pragma unroll
        for (int j = 0; j < 16; ++j) {
            int c = q4 + 4 * j;
            Ps[rA * LDT + c] = sA[j];
            Ps[rB * LDT + c] = sB[j];
        }
        __syncthreads();

        #pragma unroll 4
        for (int c = 0; c < 64; ++c) {
            unsigned long long pa2 = bcast2(Ps[rA * LDT + c]);
            unsigned long long pb2 = bcast2(Ps[rB * LDT + c]);
            const ulonglong2* vp = (const ulonglong2*)&Vs[c * LDT + q4 * 16];
            #pragma unroll
            for (int ii = 0; ii < 4; ++ii) {
                ulonglong2 vv = vp[ii];
                fma2(o2A[2 * ii + 0], pa2, vv.x);
                fma2(o2A[2 * ii + 1], pa2, vv.y);
                fma2(o2B[2 * ii + 0], pb2, vv.x);
                fma2(o2B[2 * ii + 1], pb2, vv.y);
            }
        }
    }

    const unsigned long long invA2 = bcast2(1.0f / lA);
    const unsigned long long invB2 = bcast2(1.0f / lB);
    const int b = bh >> 4, h = bh & 15;
    unsigned long long* cA = (unsigned long long*)(g_c + ((size_t)b * S_ + (qt * 64 + rA)) * D_ + h * DH_ + q4 * 16);
    unsigned long long* cB = (unsigned long long*)(g_c + ((size_t)b * S_ + (qt * 64 + rB)) * D_ + h * DH_ + q4 * 16);
    #pragma unroll
    for (int i = 0; i < 8; ++i) {
        unsigned long long wa, wb;
        mul2(wa, o2A[i], invA2);
        mul2(wb, o2B[i], invB2);
        cA[i] = wa;
        cB[i] = wb;
    }
}

// ============================================================
extern "C" void kernel_launch(void* const* d_in, const int* in_sizes, int n_in,
                              void* d_out, int out_size)
{
    const float* x  = (const float*)d_in[0];
    const float* Wq = (const float*)d_in[1];
    const float* Wk = (const float*)d_in[2];
    const float* Wv = (const float*)d_in[3];
    const float* Wo = (const float*)d_in[4];
    const float* bo = (const float*)d_in[5];
    float* out = (float*)d_out;

    cudaFuncSetAttribute(attn_kernel, cudaFuncAttributeMaxDynamicSharedMemorySize, ATTN_SMEM);

    qkv_mma_kernel<<<dim3(MROWS / 128, H_ / 2, 3), 256>>>(x, Wq, Wk, Wv);
    attn_kernel<<<dim3(S_ / 64, B_ * H_), 128, ATTN_SMEM>>>();
    out_proj_mma_kernel<<<dim3(MROWS / 128, D_ / 128), 256>>>(Wo, bo, out);
}

// round 5
// speedup vs baseline: 2.5871x; 2.0644x over previous
#include <cuda_runtime.h>
#include <cuda_bf16.h>
#include <cstdint>

#define B_ 4
#define S_ 2048
#define D_ 1024
#define H_ 16
#define DH_ 64
#define MROWS (B_ * S_)
#define QKV_ELEMS (B_ * H_ * S_ * DH_)
#define C_ELEMS   (B_ * S_ * D_)

__device__ float g_q[QKV_ELEMS];
__device__ float g_k[QKV_ELEMS];
__device__ float g_v[QKV_ELEMS];
__device__ float g_c[C_ELEMS];

// ================= helpers =================
__device__ __forceinline__ uint32_t smem_u32(const void* p) {
    uint32_t a;
    asm("{ .reg .u64 t; cvta.to.shared.u64 t, %1; cvt.u32.u64 %0, t; }" : "=r"(a) : "l"(p));
    return a;
}
__device__ __forceinline__ void bsplit(float v, float& h, float& l) {
    __nv_bfloat16 bh = __float2bfloat16(v);
    h = __bfloat162float(bh);
    l = v - h;
}
__device__ __forceinline__ uint32_t packbf(float lo_elem, float hi_elem) {
    uint32_t r;
    asm("cvt.rn.bf16x2.f32 %0, %1, %2;" : "=r"(r) : "f"(hi_elem), "f"(lo_elem));
    return r;
}
#define LDSM_X4(r0, r1, r2, r3, addr) \
    asm volatile("ldmatrix.sync.aligned.m8n8.x4.shared.b16 {%0,%1,%2,%3}, [%4];" \
        : "=r"(r0), "=r"(r1), "=r"(r2), "=r"(r3) : "r"(addr))
#define LDSM_X4_T(r0, r1, r2, r3, addr) \
    asm volatile("ldmatrix.sync.aligned.m8n8.x4.trans.shared.b16 {%0,%1,%2,%3}, [%4];" \
        : "=r"(r0), "=r"(r1), "=r"(r2), "=r"(r3) : "r"(addr))

__device__ __forceinline__ void mma16816(float* c,
    uint32_t a0, uint32_t a1, uint32_t a2, uint32_t a3, uint32_t b0, uint32_t b1)
{
    asm volatile(
        "mma.sync.aligned.m16n8k16.row.col.f32.bf16.bf16.f32 "
        "{%0,%1,%2,%3}, {%4,%5,%6,%7}, {%8,%9}, {%0,%1,%2,%3};"
        : "+f"(c[0]), "+f"(c[1]), "+f"(c[2]), "+f"(c[3])
        : "r"(a0), "r"(a1), "r"(a2), "r"(a3), "r"(b0), "r"(b1));
}

__device__ __forceinline__ void split_store(uint32_t* smw, int w, int lo_off, float4 v) {
    float hx, lx, hy, ly, hz, lz, hw, lw;
    bsplit(v.x, hx, lx); bsplit(v.y, hy, ly);
    bsplit(v.z, hz, lz); bsplit(v.w, hw, lw);
    smw[w]              = packbf(hx, hy);
    smw[w + 1]          = packbf(hz, hw);
    smw[w + lo_off]     = packbf(lx, ly);
    smw[w + lo_off + 1] = packbf(lz, lw);
}

// ============================================================
// Projection GEMM machinery (R4, proven): 128x128 tile, BK=32.
// ============================================================
#define SROW 20   // words per smem row (40 halves = 80B)
#define NKT (D_ / 32)

struct MmaTiles {
    uint32_t Ah[128 * SROW];
    uint32_t Al[128 * SROW];
    uint32_t Bh[128 * SROW];
    uint32_t Bl[128 * SROW];
};

__device__ __forceinline__ void load_a_tile(MmaTiles* t, const float* src, int ld, int k0, int m0, int tid)
{
    #pragma unroll
    for (int i = 0; i < 4; ++i) {
        int idx = tid + i * 256;
        int r = idx >> 3, c4 = idx & 7;
        float4 v = *(const float4*)(src + (size_t)(m0 + r) * ld + k0 + c4 * 4);
        float hx, lx, hy, ly, hz, lz, hw, lw;
        bsplit(v.x, hx, lx); bsplit(v.y, hy, ly);
        bsplit(v.z, hz, lz); bsplit(v.w, hw, lw);
        int w = r * SROW + c4 * 2;
        t->Ah[w]     = packbf(hx, hy);
        t->Ah[w + 1] = packbf(hz, hw);
        t->Al[w]     = packbf(lx, ly);
        t->Al[w + 1] = packbf(lz, lw);
    }
}

__device__ __forceinline__ void mma_phase(MmaTiles* t, float acc[4][4][4], int wid, int lane)
{
    const int warp_m = wid & 1;
    const int warp_n = wid >> 1;
    const uint32_t base = smem_u32(t);
    const uint32_t a_hi_b = base;
    const uint32_t a_lo_b = base + 128 * SROW * 4;
    const uint32_t b_hi_b = base + 2 * 128 * SROW * 4;
    const uint32_t b_lo_b = base + 3 * 128 * SROW * 4;

    const int a_row = warp_m * 64 + (lane & 15);
    const int a_kh  = (lane >> 4) << 3;
    const int b_row = warp_n * 32 + (lane & 7) + ((lane >> 4) << 3);
    const int b_kh  = ((lane >> 3) & 1) << 3;

    #pragma unroll
    for (int ks = 0; ks < 2; ++ks) {
        const int koff = ks * 16;
        uint32_t ah[4][4], bh[2][4], bl[2][4];
        #pragma unroll
        for (int i = 0; i < 4; ++i) {
            uint32_t addr = a_hi_b + ((a_row + i * 16) * 40 + koff + a_kh) * 2;
            LDSM_X4(ah[i][0], ah[i][1], ah[i][2], ah[i][3], addr);
        }
        #pragma unroll
        for (int jj = 0; jj < 2; ++jj) {
            uint32_t addr = b_hi_b + ((b_row + jj * 16) * 40 + koff + b_kh) * 2;
            LDSM_X4(bh[jj][0], bh[jj][1], bh[jj][2], bh[jj][3], addr);
            uint32_t addr2 = b_lo_b + ((b_row + jj * 16) * 40 + koff + b_kh) * 2;
            LDSM_X4(bl[jj][0], bl[jj][1], bl[jj][2], bl[jj][3], addr2);
        }
        #pragma unroll
        for (int i = 0; i < 4; ++i)
            #pragma unroll
            for (int j = 0; j < 4; ++j) {
                int jj = j >> 1, s = (j & 1) * 2;
                mma16816(acc[i][j], ah[i][0], ah[i][1], ah[i][2], ah[i][3], bh[jj][s], bh[jj][s + 1]);
                mma16816(acc[i][j], ah[i][0], ah[i][1], ah[i][2], ah[i][3], bl[jj][s], bl[jj][s + 1]);
            }
        #pragma unroll
        for (int i = 0; i < 4; ++i) {
            uint32_t addr = a_lo_b + ((a_row + i * 16) * 40 + koff + a_kh) * 2;
            LDSM_X4(ah[i][0], ah[i][1], ah[i][2], ah[i][3], addr);
        }
        #pragma unroll
        for (int i = 0; i < 4; ++i)
            #pragma unroll
            for (int j = 0; j < 4; ++j) {
                int jj = j >> 1, s = (j & 1) * 2;
                mma16816(acc[i][j], ah[i][0], ah[i][1], ah[i][2], ah[i][3], bh[jj][s], bh[jj][s + 1]);
            }
    }
}

// ============================================================
// Kernel 1: QKV projection (unchanged R4). grid = (64, 8, 3)
// ============================================================
__global__ __launch_bounds__(256, 1) void qkv_mma_kernel(
    const float* __restrict__ x,
    const float* __restrict__ Wq,
    const float* __restrict__ Wk,
    const float* __restrict__ Wv)
{
    __shared__ MmaTiles t;
    const int tid = threadIdx.x;
    const int wid = tid >> 5;
    const int lane = tid & 31;

    const int z = blockIdx.z;
    const float* W = (z == 0) ? Wq : ((z == 1) ? Wk : Wv);
    float* outp = (z == 0) ? g_q : ((z == 1) ? g_k : g_v);
    const float scale = (z == 0) ? 0.125f : 1.0f;
    const int hp = blockIdx.y;
    const int m0 = blockIdx.x * 128;

    float acc[4][4][4];
    #pragma unroll
    for (int i = 0; i < 4; ++i)
        #pragma unroll
        for (int j = 0; j < 4; ++j)
            #pragma unroll
            for (int q = 0; q < 4; ++q) acc[i][j][q] = 0.f;

    const int e_loc = tid & 127;
    const int kc = tid >> 7;
    const int head = hp * 2 + (e_loc >> 6);
    const int e = e_loc & 63;
    const float* wcol = W + (size_t)head * (D_ * DH_) + e;

    for (int kt = 0; kt < NKT; ++kt) {
        const int k0 = kt * 32;
        if (kt) __syncthreads();

        load_a_tile(&t, x, D_, k0, m0, tid);

        #pragma unroll
        for (int i = 0; i < 16; i += 2) {
            int k = kc * 16 + i;
            float v0 = wcol[(size_t)(k0 + k) * DH_];
            float v1 = wcol[(size_t)(k0 + k + 1) * DH_];
            float h0, l0, h1, l1;
            bsplit(v0, h0, l0); bsplit(v1, h1, l1);
            int w = e_loc * SROW + k / 2;
            t.Bh[w] = packbf(h0, h1);
            t.Bl[w] = packbf(l0, l1);
        }
        __syncthreads();

        mma_phase(&t, acc, wid, lane);
    }

    const int warp_m = wid & 1;
    const int warp_n = wid >> 1;
    #pragma unroll
    for (int i = 0; i < 4; ++i) {
        #pragma unroll
        for (int j = 0; j < 4; ++j) {
            int r0 = m0 + warp_m * 64 + i * 16 + (lane >> 2);
            int col = warp_n * 32 + j * 8 + (lane & 3) * 2;
            int hh = hp * 2 + (col >> 6);
            int ee = col & 63;
            {
                int b = r0 >> 11, s = r0 & 2047;
                float2 v; v.x = acc[i][j][0] * scale; v.y = acc[i][j][1] * scale;
                *(float2*)(outp + (((size_t)(b * H_ + hh) * S_ + s) * DH_) + ee) = v;
            }
            {
                int r1 = r0 + 8;
                int b = r1 >> 11, s = r1 & 2047;
                float2 v; v.x = acc[i][j][2] * scale; v.y = acc[i][j][3] * scale;
                *(float2*)(outp + (((size_t)(b * H_ + hh) * S_ + s) * DH_) + ee) = v;
            }
        }
    }
}

// ============================================================
// Kernel 3: output projection (unchanged R4). grid = (64, 8)
// ============================================================
__global__ __launch_bounds__(256, 1) void out_proj_mma_kernel(
    const float* __restrict__ Wo,
    const float* __restrict__ bo,
    float* __restrict__ out)
{
    __shared__ MmaTiles t;
    const int tid = threadIdx.x;
    const int wid = tid >> 5;
    const int lane = tid & 31;

    const int n0 = blockIdx.y * 128;
    const int m0 = blockIdx.x * 128;

    float acc[4][4][4];
    #pragma unroll
    for (int i = 0; i < 4; ++i)
        #pragma unroll
        for (int j = 0; j < 4; ++j)
            #pragma unroll
            for (int q = 0; q < 4; ++q) acc[i][j][q] = 0.f;

    const int e_loc = tid & 127;
    const int kc = tid >> 7;
    const float* wcol = Wo + n0 + e_loc;

    for (int kt = 0; kt < NKT; ++kt) {
        const int k0 = kt * 32;
        if (kt) __syncthreads();

        load_a_tile(&t, g_c, D_, k0, m0, tid);

        #pragma unroll
        for (int i = 0; i < 16; i += 2) {
            int k = kc * 16 + i;
            float v0 = wcol[(size_t)(k0 + k) * D_];
            float v1 = wcol[(size_t)(k0 + k + 1) * D_];
            float h0, l0, h1, l1;
            bsplit(v0, h0, l0); bsplit(v1, h1, l1);
            int w = e_loc * SROW + k / 2;
            t.Bh[w] = packbf(h0, h1);
            t.Bl[w] = packbf(l0, l1);
        }
        __syncthreads();

        mma_phase(&t, acc, wid, lane);
    }

    const int warp_m = wid & 1;
    const int warp_n = wid >> 1;
    #pragma unroll
    for (int i = 0; i < 4; ++i) {
        #pragma unroll
        for (int j = 0; j < 4; ++j) {
            int r0 = m0 + warp_m * 64 + i * 16 + (lane >> 2);
            int col = n0 + warp_n * 32 + j * 8 + (lane & 3) * 2;
            float b0 = bo[col], b1 = bo[col + 1];
            {
                float2 v; v.x = acc[i][j][0] + b0; v.y = acc[i][j][1] + b1;
                *(float2*)(out + (size_t)r0 * D_ + col) = v;
            }
            {
                float2 v; v.x = acc[i][j][2] + b0; v.y = acc[i][j][3] + b1;
                *(float2*)(out + (size_t)(r0 + 8) * D_ + col) = v;
            }
        }
    }
}

// ============================================================
// Kernel 2: causal flash attention on mma.sync (bf16 split-3).
// Block: 128 q-rows of one (b,h), 8 warps (16 rows each), KV tiles of 64.
// Smem (bytes): Qh 0, Ql 18432, Kh 36864, Kl 46080, Vh 55296, Vl 64512.
// Row stride 144B (72 halves / 36 words) -> conflict-free ldmatrix.
// ============================================================
#define ATTN_SMEM 73728
#define QH_W 0
#define QL_W 4608
#define KH_W 9216
#define KL_W 11520
#define VH_W 13824
#define VL_W 16128

__global__ __launch_bounds__(256, 1) void attn_mma_kernel()
{
    extern __shared__ char sm[];
    uint32_t* smw = (uint32_t*)sm;
    const uint32_t smb = smem_u32(sm);
    const int tid = threadIdx.x;
    const int wm = tid >> 5;      // warp -> rows wm*16..+15
    const int lane = tid & 31;

    const int bh = blockIdx.y;
    const int qb = (gridDim.x - 1) - blockIdx.x;   // 0..15, big first
    const int kmax = 2 * qb + 2;

    const uint32_t Qh_b = smb;
    const uint32_t Ql_b = smb + 18432;
    const uint32_t Kh_b = smb + 36864;
    const uint32_t Kl_b = smb + 46080;
    const uint32_t Vh_b = smb + 55296;
    const uint32_t Vl_b = smb + 64512;

    // ---- load Q tile 128x64, split bf16 ----
    const float* qg = g_q + ((size_t)bh * S_ + qb * 128) * DH_;
    #pragma unroll
    for (int i = 0; i < 8; ++i) {
        int idx = tid + i * 256;
        int r = idx >> 4, c4 = idx & 15;
        float4 v = *(const float4*)(qg + r * 64 + c4 * 4);
        split_store(smw, QH_W + r * 36 + c4 * 2, QL_W - QH_W, v);
    }
    __syncthreads();

    // ---- Q fragments into registers (held for whole block) ----
    uint32_t qh[4][4], ql[4][4];
    {
        const int ar = wm * 16 + (lane & 15);
        const int koff = (lane >> 4) << 3;
        #pragma unroll
        for (int ks = 0; ks < 4; ++ks) {
            LDSM_X4(qh[ks][0], qh[ks][1], qh[ks][2], qh[ks][3],
                    Qh_b + ar * 144 + (ks * 16 + koff) * 2);
            LDSM_X4(ql[ks][0], ql[ks][1], ql[ks][2], ql[ks][3],
                    Ql_b + ar * 144 + (ks * 16 + koff) * 2);
        }
    }

    float mA = -3.0e38f, mB = -3.0e38f, lA = 0.f, lB = 0.f;
    float oacc[8][4];
    #pragma unroll
    for (int t = 0; t < 8; ++t)
        #pragma unroll
        for (int q = 0; q < 4; ++q) oacc[t][q] = 0.f;

    // ldmatrix lane-address components
    const int kb_row  = (lane & 7) + ((lane >> 4) << 3);        // + np*16
    const int kb_koff = ((lane >> 3) & 1) << 3;                 // + ks*16
    const int vb_row  = (lane & 7) + (((lane >> 3) & 1) << 3);  // + ks*16
    const int vb_eoff = (lane >> 4) << 3;                       // + ep*16

    const int rA_g = qb * 128 + wm * 16 + (lane >> 2);

    for (int kt = 0; kt < kmax; ++kt) {
        __syncthreads();   // previous iteration's ldmatrix reads done
        const float* kg = g_k + ((size_t)bh * S_ + kt * 64) * DH_;
        const float* vg = g_v + ((size_t)bh * S_ + kt * 64) * DH_;
        #pragma unroll
        for (int i = 0; i < 4; ++i) {
            int idx = tid + i * 256;
            int r = idx >> 4, c4 = idx & 15;
            float4 v = *(const float4*)(kg + r * 64 + c4 * 4);
            split_store(smw, KH_W + r * 36 + c4 * 2, KL_W - KH_W, v);
            float4 u = *(const float4*)(vg + r * 64 + c4 * 4);
            split_store(smw, VH_W + r * 36 + c4 * 2, VL_W - VH_W, u);
        }
        __syncthreads();

        // ---- S = Q K^T (split-3) ----
        float sacc[8][4];
        #pragma unroll
        for (int t = 0; t < 8; ++t)
            #pragma unroll
            for (int q = 0; q < 4; ++q) sacc[t][q] = 0.f;

        #pragma unroll
        for (int ks = 0; ks < 4; ++ks) {
            #pragma unroll
            for (int np = 0; np < 4; ++np) {
                uint32_t row = np * 16 + kb_row;
                uint32_t ko  = ks * 16 + kb_koff;
                uint32_t b0, b1, b2, b3, c0, c1, c2, c3;
                LDSM_X4(b0, b1, b2, b3, Kh_b + row * 144 + ko * 2);
                LDSM_X4(c0, c1, c2, c3, Kl_b + row * 144 + ko * 2);
                mma16816(sacc[2 * np],     qh[ks][0], qh[ks][1], qh[ks][2], qh[ks][3], b0, b1);
                mma16816(sacc[2 * np],     qh[ks][0], qh[ks][1], qh[ks][2], qh[ks][3], c0, c1);
                mma16816(sacc[2 * np],     ql[ks][0], ql[ks][1], ql[ks][2], ql[ks][3], b0, b1);
                mma16816(sacc[2 * np + 1], qh[ks][0], qh[ks][1], qh[ks][2], qh[ks][3], b2, b3);
                mma16816(sacc[2 * np + 1], qh[ks][0], qh[ks][1], qh[ks][2], qh[ks][3], c2, c3);
                mma16816(sacc[2 * np + 1], ql[ks][0], ql[ks][1], ql[ks][2], ql[ks][3], b2, b3);
            }
        }

        // ---- causal mask (diagonal tiles only) ----
        if (kt >= 2 * qb) {
            const int c0g = kt * 64 + 2 * (lane & 3);
            #pragma unroll
            for (int t = 0; t < 8; ++t) {
                int c = c0g + 8 * t;
                if (c     > rA_g)     sacc[t][0] = -3.0e38f;
                if (c + 1 > rA_g)     sacc[t][1] = -3.0e38f;
                if (c     > rA_g + 8) sacc[t][2] = -3.0e38f;
                if (c + 1 > rA_g + 8) sacc[t][3] = -3.0e38f;
            }
        }

        // ---- online softmax (row owned by 4 lanes: lane&3) ----
        float mtA = -3.0e38f, mtB = -3.0e38f;
        #pragma unroll
        for (int t = 0; t < 8; ++t) {
            mtA = fmaxf(mtA, fmaxf(sacc[t][0], sacc[t][1]));
            mtB = fmaxf(mtB, fmaxf(sacc[t][2], sacc[t][3]));
        }
        mtA = fmaxf(mtA, __shfl_xor_sync(0xffffffffu, mtA, 1));
        mtA = fmaxf(mtA, __shfl_xor_sync(0xffffffffu, mtA, 2));
        mtB = fmaxf(mtB, __shfl_xor_sync(0xffffffffu, mtB, 1));
        mtB = fmaxf(mtB, __shfl_xor_sync(0xffffffffu, mtB, 2));

        float mnA = fmaxf(mA, mtA), mnB = fmaxf(mB, mtB);
        float corrA = __expf(mA - mnA), corrB = __expf(mB - mnB);

        float rsA = 0.f, rsB = 0.f;
        #pragma unroll
        for (int t = 0; t < 8; ++t) {
            float p0 = __expf(sacc[t][0] - mnA); sacc[t][0] = p0; rsA += p0;
            float p1 = __expf(sacc[t][1] - mnA); sacc[t][1] = p1; rsA += p1;
            float p2 = __expf(sacc[t][2] - mnB); sacc[t][2] = p2; rsB += p2;
            float p3 = __expf(sacc[t][3] - mnB); sacc[t][3] = p3; rsB += p3;
        }
        rsA += __shfl_xor_sync(0xffffffffu, rsA, 1);
        rsA += __shfl_xor_sync(0xffffffffu, rsA, 2);
        rsB += __shfl_xor_sync(0xffffffffu, rsB, 1);
        rsB += __shfl_xor_sync(0xffffffffu, rsB, 2);

        lA = lA * corrA + rsA;
        lB = lB * corrB + rsB;
        #pragma unroll
        for (int t = 0; t < 8; ++t) {
            oacc[t][0] *= corrA; oacc[t][1] *= corrA;
            oacc[t][2] *= corrB; oacc[t][3] *= corrB;
        }
        mA = mnA; mB = mnB;

        // ---- O += P V (split-3; P frags built in registers) ----
        #pragma unroll
        for (int ks = 0; ks < 4; ++ks) {
            uint32_t pfh[4], pfl[4];
            {
                float h00, l00, h01, l01, h10, l10, h11, l11;
                bsplit(sacc[2 * ks][0], h00, l00); bsplit(sacc[2 * ks][1], h01, l01);
                bsplit(sacc[2 * ks][2], h10, l10); bsplit(sacc[2 * ks][3], h11, l11);
                pfh[0] = packbf(h00, h01); pfl[0] = packbf(l00, l01);
                pfh[1] = packbf(h10, h11); pfl[1] = packbf(l10, l11);
                bsplit(sacc[2 * ks + 1][0], h00, l00); bsplit(sacc[2 * ks + 1][1], h01, l01);
                bsplit(sacc[2 * ks + 1][2], h10, l10); bsplit(sacc[2 * ks + 1][3], h11, l11);
                pfh[2] = packbf(h00, h01); pfl[2] = packbf(l00, l01);
                pfh[3] = packbf(h10, h11); pfl[3] = packbf(l10, l11);
            }
            #pragma unroll
            for (int ep = 0; ep < 4; ++ep) {
                uint32_t row = ks * 16 + vb_row;
                uint32_t eo  = ep * 16 + vb_eoff;
                uint32_t v0, v1, v2, v3, w0, w1, w2, w3;
                LDSM_X4_T(v0, v1, v2, v3, Vh_b + row * 144 + eo * 2);
                LDSM_X4_T(w0, w1, w2, w3, Vl_b + row * 144 + eo * 2);
                mma16816(oacc[2 * ep],     pfh[0], pfh[1], pfh[2], pfh[3], v0, v1);
                mma16816(oacc[2 * ep],     pfh[0], pfh[1], pfh[2], pfh[3], w0, w1);
                mma16816(oacc[2 * ep],     pfl[0], pfl[1], pfl[2], pfl[3], v0, v1);
                mma16816(oacc[2 * ep + 1], pfh[0], pfh[1], pfh[2], pfh[3], v2, v3);
                mma16816(oacc[2 * ep + 1], pfh[0], pfh[1], pfh[2], pfh[3], w2, w3);
                mma16816(oacc[2 * ep + 1], pfl[0], pfl[1], pfl[2], pfl[3], v2, v3);
            }
        }
    }

    // ---- finalize: g_c[b, s, h*64 + e] ----
    const float invA = 1.0f / lA;
    const float invB = 1.0f / lB;
    const int b = bh >> 4, h = bh & 15;
    const int e0 = 2 * (lane & 3);
    float* baseA = g_c + ((size_t)b * S_ + rA_g) * D_ + h * DH_;
    float* baseB = g_c + ((size_t)b * S_ + rA_g + 8) * D_ + h * DH_;
    #pragma unroll
    for (int t = 0; t < 8; ++t) {
        int e = 8 * t + e0;
        float2 va; va.x = oacc[t][0] * invA; va.y = oacc[t][1] * invA;
        float2 vb; vb.x = oacc[t][2] * invB; vb.y = oacc[t][3] * invB;
        *(float2*)(baseA + e) = va;
        *(float2*)(baseB + e) = vb;
    }
}

// ============================================================
extern "C" void kernel_launch(void* const* d_in, const int* in_sizes, int n_in,
                              void* d_out, int out_size)
{
    const float* x  = (const float*)d_in[0];
    const float* Wq = (const float*)d_in[1];
    const float* Wk = (const float*)d_in[2];
    const float* Wv = (const float*)d_in[3];
    const float* Wo = (const float*)d_in[4];
    const float* bo = (const float*)d_in[5];
    float* out = (float*)d_out;

    cudaFuncSetAttribute(attn_mma_kernel, cudaFuncAttributeMaxDynamicSharedMemorySize, ATTN_SMEM);

    qkv_mma_kernel<<<dim3(MROWS / 128, H_ / 2, 3), 256>>>(x, Wq, Wk, Wv);
    attn_mma_kernel<<<dim3(S_ / 128, B_ * H_), 256, ATTN_SMEM>>>();
    out_proj_mma_kernel<<<dim3(MROWS / 128, D_ / 128), 256>>>(Wo, bo, out);
}

// round 6
// speedup vs baseline: 3.3028x; 1.2767x over previous
#include <cuda_runtime.h>
#include <cuda_bf16.h>
#include <cstdint>

#define B_ 4
#define S_ 2048
#define D_ 1024
#define H_ 16
#define DH_ 64
#define MROWS (B_ * S_)
#define QKV_ELEMS (B_ * H_ * S_ * DH_)   // 8388608
#define C_ELEMS   (B_ * S_ * D_)         // 8388608

// -------- bf16 hi/lo scratch (no allocation) --------
__device__ __nv_bfloat16 g_xh[C_ELEMS],  g_xl[C_ELEMS];
__device__ __nv_bfloat16 g_wt_h[3 * H_ * DH_ * D_], g_wt_l[3 * H_ * DH_ * D_];
__device__ __nv_bfloat16 g_wo_h[D_ * D_], g_wo_l[D_ * D_];
__device__ __nv_bfloat16 g_qh[QKV_ELEMS], g_ql[QKV_ELEMS];
__device__ __nv_bfloat16 g_kh[QKV_ELEMS], g_kl[QKV_ELEMS];
__device__ __nv_bfloat16 g_vh[QKV_ELEMS], g_vl[QKV_ELEMS];
__device__ __nv_bfloat16 g_ch[C_ELEMS],  g_cl[C_ELEMS];

// ================= helpers =================
__device__ __forceinline__ uint32_t smem_u32(const void* p) {
    uint32_t a;
    asm("{ .reg .u64 t; cvta.to.shared.u64 t, %1; cvt.u32.u64 %0, t; }" : "=r"(a) : "l"(p));
    return a;
}
__device__ __forceinline__ void bsplit(float v, float& h, float& l) {
    __nv_bfloat16 bh = __float2bfloat16(v);
    h = __bfloat162float(bh);
    l = v - h;
}
__device__ __forceinline__ uint32_t packbf(float lo_elem, float hi_elem) {
    uint32_t r;
    asm("cvt.rn.bf16x2.f32 %0, %1, %2;" : "=r"(r) : "f"(hi_elem), "f"(lo_elem));
    return r;
}
#define LDSM_X4(r0, r1, r2, r3, addr) \
    asm volatile("ldmatrix.sync.aligned.m8n8.x4.shared.b16 {%0,%1,%2,%3}, [%4];" \
        : "=r"(r0), "=r"(r1), "=r"(r2), "=r"(r3) : "r"(addr))
#define LDSM_X4_T(r0, r1, r2, r3, addr) \
    asm volatile("ldmatrix.sync.aligned.m8n8.x4.trans.shared.b16 {%0,%1,%2,%3}, [%4];" \
        : "=r"(r0), "=r"(r1), "=r"(r2), "=r"(r3) : "r"(addr))
#define CP_A16(sa, gp) asm volatile("cp.async.ca.shared.global [%0], [%1], 16;" :: "r"(sa), "l"(gp))
#define CP_COMMIT()    asm volatile("cp.async.commit_group;" ::: "memory")
#define CP_WAIT(n)     asm volatile("cp.async.wait_group %0;" :: "n"(n) : "memory")

__device__ __forceinline__ void mma16816(float* c,
    uint32_t a0, uint32_t a1, uint32_t a2, uint32_t a3, uint32_t b0, uint32_t b1)
{
    asm volatile(
        "mma.sync.aligned.m16n8k16.row.col.f32.bf16.bf16.f32 "
        "{%0,%1,%2,%3}, {%4,%5,%6,%7}, {%8,%9}, {%0,%1,%2,%3};"
        : "+f"(c[0]), "+f"(c[1]), "+f"(c[2]), "+f"(c[3])
        : "r"(a0), "r"(a1), "r"(a2), "r"(a3), "r"(b0), "r"(b1));
}

// ============================================================
// Preconversion kernels
// ============================================================
__global__ __launch_bounds__(256) void conv_x_kernel(const float* __restrict__ x)
{
    int i = blockIdx.x * 256 + threadIdx.x;     // over float4s (2M)
    float4 v = *(const float4*)(x + 4 * (size_t)i);
    float hx, lx, hy, ly, hz, lz, hw, lw;
    bsplit(v.x, hx, lx); bsplit(v.y, hy, ly);
    bsplit(v.z, hz, lz); bsplit(v.w, hw, lw);
    uint2 wh, wl;
    wh.x = packbf(hx, hy); wh.y = packbf(hz, hw);
    wl.x = packbf(lx, ly); wl.y = packbf(lz, lw);
    *(uint2*)(g_xh + 4 * (size_t)i) = wh;
    *(uint2*)(g_xl + 4 * (size_t)i) = wl;
}

// transpose W[h][d][e] (48 matrices of 1024x64) -> WT[(z*16+h)*64+e][d]
__global__ __launch_bounds__(256) void conv_w_kernel(
    const float* __restrict__ Wq, const float* __restrict__ Wk, const float* __restrict__ Wv)
{
    __shared__ float ts[64][65];
    const int tid = threadIdx.x;
    const int d0 = blockIdx.x * 64;
    const int h  = blockIdx.y;
    const int z  = blockIdx.z;
    const float* W = (z == 0) ? Wq : ((z == 1) ? Wk : Wv);
    const float* src = W + (size_t)h * D_ * DH_;

    #pragma unroll
    for (int i = 0; i < 4; ++i) {
        int idx = tid + i * 256;
        int rr = idx >> 4, cc = idx & 15;
        float4 v = *(const float4*)(src + (size_t)(d0 + rr) * DH_ + cc * 4);
        ts[rr][cc * 4 + 0] = v.x; ts[rr][cc * 4 + 1] = v.y;
        ts[rr][cc * 4 + 2] = v.z; ts[rr][cc * 4 + 3] = v.w;
    }
    __syncthreads();
    #pragma unroll
    for (int i = 0; i < 8; ++i) {
        int idx = tid + i * 256;
        int e = idx >> 5, w = idx & 31;
        float v0 = ts[2 * w][e], v1 = ts[2 * w + 1][e];
        float h0, l0, h1, l1;
        bsplit(v0, h0, l0); bsplit(v1, h1, l1);
        size_t off = ((size_t)(z * H_ + h) * DH_ + e) * D_ + d0 + 2 * w;
        *(uint32_t*)(g_wt_h + off) = packbf(h0, h1);
        *(uint32_t*)(g_wt_l + off) = packbf(l0, l1);
    }
}

// transpose Wo[d][f] -> WoT[f][d]
__global__ __launch_bounds__(256) void conv_wo_kernel(const float* __restrict__ Wo)
{
    __shared__ float ts[64][65];
    const int tid = threadIdx.x;
    const int d0 = blockIdx.x * 64;
    const int f0 = blockIdx.y * 64;

    #pragma unroll
    for (int i = 0; i < 4; ++i) {
        int idx = tid + i * 256;
        int rr = idx >> 4, cc = idx & 15;
        float4 v = *(const float4*)(Wo + (size_t)(d0 + rr) * D_ + f0 + cc * 4);
        ts[rr][cc * 4 + 0] = v.x; ts[rr][cc * 4 + 1] = v.y;
        ts[rr][cc * 4 + 2] = v.z; ts[rr][cc * 4 + 3] = v.w;
    }
    __syncthreads();
    #pragma unroll
    for (int i = 0; i < 8; ++i) {
        int idx = tid + i * 256;
        int e = idx >> 5, w = idx & 31;
        float v0 = ts[2 * w][e], v1 = ts[2 * w + 1][e];
        float h0, l0, h1, l1;
        bsplit(v0, h0, l0); bsplit(v1, h1, l1);
        size_t off = (size_t)(f0 + e) * D_ + d0 + 2 * w;
        *(uint32_t*)(g_wo_h + off) = packbf(h0, h1);
        *(uint32_t*)(g_wo_l + off) = packbf(l0, l1);
    }
}

// ============================================================
// GEMM machinery: 128x128 tile, BK=32, double-buffered cp.async.
// stage layout (bytes from stage base): Ah 0, Al 10240, Bh 20480, Bl 30720
// row stride 80B (40 halves). Stage size 40960B; 2 stages = 81920B.
// ============================================================
#define GEMM_SMEM 81920
#define NKT (D_ / 32)

__device__ __forceinline__ void gemm_load_stage(uint32_t sbase,
    const __nv_bfloat16* p0, const __nv_bfloat16* p1,
    const __nv_bfloat16* p2, const __nv_bfloat16* p3, int tid)
{
    const __nv_bfloat16* p[4] = {p0, p1, p2, p3};
    #pragma unroll
    for (int i = 0; i < 8; ++i) {
        int idx = tid + i * 256;
        int arr = idx >> 9;
        int c = idx & 511;
        int r = c >> 2, col = c & 3;
        const __nv_bfloat16* src = p[arr] + (size_t)r * D_ + col * 8;
        uint32_t sa = sbase + arr * 10240 + r * 80 + col * 16;
        CP_A16(sa, src);
    }
}

__device__ __forceinline__ void mma_phase(uint32_t sbase, float acc[4][4][4], int wid, int lane)
{
    const int warp_m = wid & 1;
    const int warp_n = wid >> 1;
    const uint32_t a_hi_b = sbase;
    const uint32_t a_lo_b = sbase + 10240;
    const uint32_t b_hi_b = sbase + 20480;
    const uint32_t b_lo_b = sbase + 30720;

    const int a_row = warp_m * 64 + (lane & 15);
    const int a_kh  = (lane >> 4) << 3;
    const int b_row = warp_n * 32 + (lane & 7) + ((lane >> 4) << 3);
    const int b_kh  = ((lane >> 3) & 1) << 3;

    #pragma unroll
    for (int ks = 0; ks < 2; ++ks) {
        const int koff = ks * 16;
        uint32_t ah[4][4], bh[2][4], bl[2][4];
        #pragma unroll
        for (int i = 0; i < 4; ++i) {
            uint32_t addr = a_hi_b + ((a_row + i * 16) * 40 + koff + a_kh) * 2;
            LDSM_X4(ah[i][0], ah[i][1], ah[i][2], ah[i][3], addr);
        }
        #pragma unroll
        for (int jj = 0; jj < 2; ++jj) {
            uint32_t addr = b_hi_b + ((b_row + jj * 16) * 40 + koff + b_kh) * 2;
            LDSM_X4(bh[jj][0], bh[jj][1], bh[jj][2], bh[jj][3], addr);
            uint32_t addr2 = b_lo_b + ((b_row + jj * 16) * 40 + koff + b_kh) * 2;
            LDSM_X4(bl[jj][0], bl[jj][1], bl[jj][2], bl[jj][3], addr2);
        }
        #pragma unroll
        for (int i = 0; i < 4; ++i)
            #pragma unroll
            for (int j = 0; j < 4; ++j) {
                int jj = j >> 1, s = (j & 1) * 2;
                mma16816(acc[i][j], ah[i][0], ah[i][1], ah[i][2], ah[i][3], bh[jj][s], bh[jj][s + 1]);
                mma16816(acc[i][j], ah[i][0], ah[i][1], ah[i][2], ah[i][3], bl[jj][s], bl[jj][s + 1]);
            }
        #pragma unroll
        for (int i = 0; i < 4; ++i) {
            uint32_t addr = a_lo_b + ((a_row + i * 16) * 40 + koff + a_kh) * 2;
            LDSM_X4(ah[i][0], ah[i][1], ah[i][2], ah[i][3], addr);
        }
        #pragma unroll
        for (int i = 0; i < 4; ++i)
            #pragma unroll
            for (int j = 0; j < 4; ++j) {
                int jj = j >> 1, s = (j & 1) * 2;
                mma16816(acc[i][j], ah[i][0], ah[i][1], ah[i][2], ah[i][3], bh[jj][s], bh[jj][s + 1]);
            }
    }
}

// ============================================================
// Kernel 1: QKV projection. grid = (64, 8, 3), block 256.
// ============================================================
__global__ __launch_bounds__(256, 1) void qkv_mma_kernel()
{
    extern __shared__ char sm[];
    const uint32_t smb = smem_u32(sm);
    const int tid = threadIdx.x;
    const int wid = tid >> 5;
    const int lane = tid & 31;

    const int z = blockIdx.z;
    const int hp = blockIdx.y;
    const int m0 = blockIdx.x * 128;

    __nv_bfloat16* outh = (z == 0) ? g_qh : ((z == 1) ? g_kh : g_vh);
    __nv_bfloat16* outl = (z == 0) ? g_ql : ((z == 1) ? g_kl : g_vl);
    const float scale = (z == 0) ? 0.125f : 1.0f;

    const __nv_bfloat16* ah = g_xh + (size_t)m0 * D_;
    const __nv_bfloat16* al = g_xl + (size_t)m0 * D_;
    const __nv_bfloat16* bh = g_wt_h + (size_t)(z * H_ + hp * 2) * DH_ * D_;
    const __nv_bfloat16* bl = g_wt_l + (size_t)(z * H_ + hp * 2) * DH_ * D_;

    float acc[4][4][4];
    #pragma unroll
    for (int i = 0; i < 4; ++i)
        #pragma unroll
        for (int j = 0; j < 4; ++j)
            #pragma unroll
            for (int q = 0; q < 4; ++q) acc[i][j][q] = 0.f;

    gemm_load_stage(smb, ah, al, bh, bl, tid);
    CP_COMMIT();

    for (int kt = 0; kt < NKT; ++kt) {
        if (kt + 1 < NKT) {
            int k1 = (kt + 1) * 32;
            gemm_load_stage(smb + ((kt + 1) & 1) * 40960,
                            ah + k1, al + k1, bh + k1, bl + k1, tid);
            CP_COMMIT();
            CP_WAIT(1);
        } else {
            CP_WAIT(0);
        }
        __syncthreads();
        mma_phase(smb + (kt & 1) * 40960, acc, wid, lane);
        __syncthreads();
    }

    const int warp_m = wid & 1;
    const int warp_n = wid >> 1;
    #pragma unroll
    for (int i = 0; i < 4; ++i) {
        #pragma unroll
        for (int j = 0; j < 4; ++j) {
            int r0 = m0 + warp_m * 64 + i * 16 + (lane >> 2);
            int col = warp_n * 32 + j * 8 + (lane & 3) * 2;
            int hh = hp * 2 + (col >> 6);
            int ee = col & 63;
            #pragma unroll
            for (int half = 0; half < 2; ++half) {
                int r = r0 + half * 8;
                int b = r >> 11, s = r & 2047;
                float v0 = acc[i][j][2 * half] * scale;
                float v1 = acc[i][j][2 * half + 1] * scale;
                float h0, l0, h1, l1;
                bsplit(v0, h0, l0); bsplit(v1, h1, l1);
                size_t off = ((size_t)(b * H_ + hh) * S_ + s) * DH_ + ee;
                *(uint32_t*)(outh + off) = packbf(h0, h1);
                *(uint32_t*)(outl + off) = packbf(l0, l1);
            }
        }
    }
}

// ============================================================
// Kernel 3: output projection. grid = (64, 8), block 256.
// ============================================================
__global__ __launch_bounds__(256, 1) void out_proj_mma_kernel(
    const float* __restrict__ bo, float* __restrict__ out)
{
    extern __shared__ char sm[];
    const uint32_t smb = smem_u32(sm);
    const int tid = threadIdx.x;
    const int wid = tid >> 5;
    const int lane = tid & 31;

    const int n0 = blockIdx.y * 128;
    const int m0 = blockIdx.x * 128;

    const __nv_bfloat16* ah = g_ch + (size_t)m0 * D_;
    const __nv_bfloat16* al = g_cl + (size_t)m0 * D_;
    const __nv_bfloat16* bh = g_wo_h + (size_t)n0 * D_;
    const __nv_bfloat16* bl = g_wo_l + (size_t)n0 * D_;

    float acc[4][4][4];
    #pragma unroll
    for (int i = 0; i < 4; ++i)
        #pragma unroll
        for (int j = 0; j < 4; ++j)
            #pragma unroll
            for (int q = 0; q < 4; ++q) acc[i][j][q] = 0.f;

    gemm_load_stage(smb, ah, al, bh, bl, tid);
    CP_COMMIT();

    for (int kt = 0; kt < NKT; ++kt) {
        if (kt + 1 < NKT) {
            int k1 = (kt + 1) * 32;
            gemm_load_stage(smb + ((kt + 1) & 1) * 40960,
                            ah + k1, al + k1, bh + k1, bl + k1, tid);
            CP_COMMIT();
            CP_WAIT(1);
        } else {
            CP_WAIT(0);
        }
        __syncthreads();
        mma_phase(smb + (kt & 1) * 40960, acc, wid, lane);
        __syncthreads();
    }

    const int warp_m = wid & 1;
    const int warp_n = wid >> 1;
    #pragma unroll
    for (int i = 0; i < 4; ++i) {
        #pragma unroll
        for (int j = 0; j < 4; ++j) {
            int r0 = m0 + warp_m * 64 + i * 16 + (lane >> 2);
            int col = n0 + warp_n * 32 + j * 8 + (lane & 3) * 2;
            float b0 = bo[col], b1 = bo[col + 1];
            {
                float2 v; v.x = acc[i][j][0] + b0; v.y = acc[i][j][1] + b1;
                *(float2*)(out + (size_t)r0 * D_ + col) = v;
            }
            {
                float2 v; v.x = acc[i][j][2] + b0; v.y = acc[i][j][3] + b1;
                *(float2*)(out + (size_t)(r0 + 8) * D_ + col) = v;
            }
        }
    }
}

// ============================================================
// Kernel 2: causal flash attention (mma.sync split-3, double-buffered KV).
// Smem: Qh 0, Ql 18432; KV stages at 36864 + st*36864:
//   Kh +0, Kl +9216, Vh +18432, Vl +27648 (rows 144B).
// ============================================================
#define ATTN_SMEM 110592

__device__ __forceinline__ void attn_load_kv(uint32_t kvb,
    const __nv_bfloat16* kh, const __nv_bfloat16* kl,
    const __nv_bfloat16* vh, const __nv_bfloat16* vl, int tid)
{
    const __nv_bfloat16* p[4] = {kh, kl, vh, vl};
    #pragma unroll
    for (int i = 0; i < 8; ++i) {
        int idx = tid + i * 256;
        int arr = idx >> 9;
        int c = idx & 511;
        int r = c >> 3, c8 = c & 7;
        const __nv_bfloat16* src = p[arr] + (size_t)r * DH_ + c8 * 8;
        uint32_t sa = kvb + arr * 9216 + r * 144 + c8 * 16;
        CP_A16(sa, src);
    }
}

__global__ __launch_bounds__(256, 1) void attn_mma_kernel()
{
    extern __shared__ char sm[];
    const uint32_t smb = smem_u32(sm);
    const int tid = threadIdx.x;
    const int wm = tid >> 5;
    const int lane = tid & 31;

    const int bh = blockIdx.y;
    const int qb = (gridDim.x - 1) - blockIdx.x;
    const int kmax = 2 * qb + 2;

    const uint32_t Qh_b = smb;
    const uint32_t Ql_b = smb + 18432;

    const __nv_bfloat16* kh_g = g_kh + (size_t)bh * S_ * DH_;
    const __nv_bfloat16* kl_g = g_kl + (size_t)bh * S_ * DH_;
    const __nv_bfloat16* vh_g = g_vh + (size_t)bh * S_ * DH_;
    const __nv_bfloat16* vl_g = g_vl + (size_t)bh * S_ * DH_;

    // prefetch KV tile 0 (stage 0)
    attn_load_kv(smb + 36864, kh_g, kl_g, vh_g, vl_g, tid);
    CP_COMMIT();

    // ---- load Q tile 128x64 hi/lo (plain copies) ----
    {
        const __nv_bfloat16* qh_g = g_qh + ((size_t)bh * S_ + qb * 128) * DH_;
        const __nv_bfloat16* ql_g = g_ql + ((size_t)bh * S_ + qb * 128) * DH_;
        #pragma unroll
        for (int i = 0; i < 4; ++i) {
            int idx = tid + i * 256;
            int r = idx >> 3, c8 = idx & 7;
            *(uint4*)(sm + (Qh_b - smb) + r * 144 + c8 * 16) =
                *(const uint4*)(qh_g + (size_t)r * DH_ + c8 * 8);
            *(uint4*)(sm + (Ql_b - smb) + r * 144 + c8 * 16) =
                *(const uint4*)(ql_g + (size_t)r * DH_ + c8 * 8);
        }
    }
    __syncthreads();

    // ---- Q fragments into registers ----
    uint32_t qh[4][4], ql[4][4];
    {
        const int ar = wm * 16 + (lane & 15);
        const int koff = (lane >> 4) << 3;
        #pragma unroll
        for (int ks = 0; ks < 4; ++ks) {
            LDSM_X4(qh[ks][0], qh[ks][1], qh[ks][2], qh[ks][3],
                    Qh_b + ar * 144 + (ks * 16 + koff) * 2);
            LDSM_X4(ql[ks][0], ql[ks][1], ql[ks][2], ql[ks][3],
                    Ql_b + ar * 144 + (ks * 16 + koff) * 2);
        }
    }

    float mA = -3.0e38f, mB = -3.0e38f, lA = 0.f, lB = 0.f;
    float oacc[8][4];
    #pragma unroll
    for (int t = 0; t < 8; ++t)
        #pragma unroll
        for (int q = 0; q < 4; ++q) oacc[t][q] = 0.f;

    const int kb_row  = (lane & 7) + ((lane >> 4) << 3);
    const int kb_koff = ((lane >> 3) & 1) << 3;
    const int vb_row  = (lane & 7) + (((lane >> 3) & 1) << 3);
    const int vb_eoff = (lane >> 4) << 3;

    const int rA_g = qb * 128 + wm * 16 + (lane >> 2);

    for (int kt = 0; kt < kmax; ++kt) {
        if (kt + 1 < kmax) {
            size_t koff = (size_t)(kt + 1) * 64 * DH_;
            attn_load_kv(smb + 36864 + ((kt + 1) & 1) * 36864,
                         kh_g + koff, kl_g + koff, vh_g + koff, vl_g + koff, tid);
            CP_COMMIT();
            CP_WAIT(1);
        } else {
            CP_WAIT(0);
        }
        __syncthreads();

        const uint32_t kvb = smb + 36864 + (kt & 1) * 36864;
        const uint32_t Kh_b = kvb, Kl_b = kvb + 9216, Vh_b = kvb + 18432, Vl_b = kvb + 27648;

        // ---- S = Q K^T (split-3) ----
        float sacc[8][4];
        #pragma unroll
        for (int t = 0; t < 8; ++t)
            #pragma unroll
            for (int q = 0; q < 4; ++q) sacc[t][q] = 0.f;

        #pragma unroll
        for (int ks = 0; ks < 4; ++ks) {
            #pragma unroll
            for (int np = 0; np < 4; ++np) {
                uint32_t row = np * 16 + kb_row;
                uint32_t ko  = ks * 16 + kb_koff;
                uint32_t b0, b1, b2, b3, c0, c1, c2, c3;
                LDSM_X4(b0, b1, b2, b3, Kh_b + row * 144 + ko * 2);
                LDSM_X4(c0, c1, c2, c3, Kl_b + row * 144 + ko * 2);
                mma16816(sacc[2 * np],     qh[ks][0], qh[ks][1], qh[ks][2], qh[ks][3], b0, b1);
                mma16816(sacc[2 * np],     qh[ks][0], qh[ks][1], qh[ks][2], qh[ks][3], c0, c1);
                mma16816(sacc[2 * np],     ql[ks][0], ql[ks][1], ql[ks][2], ql[ks][3], b0, b1);
                mma16816(sacc[2 * np + 1], qh[ks][0], qh[ks][1], qh[ks][2], qh[ks][3], b2, b3);
                mma16816(sacc[2 * np + 1], qh[ks][0], qh[ks][1], qh[ks][2], qh[ks][3], c2, c3);
                mma16816(sacc[2 * np + 1], ql[ks][0], ql[ks][1], ql[ks][2], ql[ks][3], b2, b3);
            }
        }

        if (kt >= 2 * qb) {
            const int c0g = kt * 64 + 2 * (lane & 3);
            #pragma unroll
            for (int t = 0; t < 8; ++t) {
                int c = c0g + 8 * t;
                if (c     > rA_g)     sacc[t][0] = -3.0e38f;
                if (c + 1 > rA_g)     sacc[t][1] = -3.0e38f;
                if (c     > rA_g + 8) sacc[t][2] = -3.0e38f;
                if (c + 1 > rA_g + 8) sacc[t][3] = -3.0e38f;
            }
        }

        float mtA = -3.0e38f, mtB = -3.0e38f;
        #pragma unroll
        for (int t = 0; t < 8; ++t) {
            mtA = fmaxf(mtA, fmaxf(sacc[t][0], sacc[t][1]));
            mtB = fmaxf(mtB, fmaxf(sacc[t][2], sacc[t][3]));
        }
        mtA = fmaxf(mtA, __shfl_xor_sync(0xffffffffu, mtA, 1));
        mtA = fmaxf(mtA, __shfl_xor_sync(0xffffffffu, mtA, 2));
        mtB = fmaxf(mtB, __shfl_xor_sync(0xffffffffu, mtB, 1));
        mtB = fmaxf(mtB, __shfl_xor_sync(0xffffffffu, mtB, 2));

        float mnA = fmaxf(mA, mtA), mnB = fmaxf(mB, mtB);
        float corrA = __expf(mA - mnA), corrB = __expf(mB - mnB);

        float rsA = 0.f, rsB = 0.f;
        #pragma unroll
        for (int t = 0; t < 8; ++t) {
            float p0 = __expf(sacc[t][0] - mnA); sacc[t][0] = p0; rsA += p0;
            float p1 = __expf(sacc[t][1] - mnA); sacc[t][1] = p1; rsA += p1;
            float p2 = __expf(sacc[t][2] - mnB); sacc[t][2] = p2; rsB += p2;
            float p3 = __expf(sacc[t][3] - mnB); sacc[t][3] = p3; rsB += p3;
        }
        rsA += __shfl_xor_sync(0xffffffffu, rsA, 1);
        rsA += __shfl_xor_sync(0xffffffffu, rsA, 2);
        rsB += __shfl_xor_sync(0xffffffffu, rsB, 1);
        rsB += __shfl_xor_sync(0xffffffffu, rsB, 2);

        lA = lA * corrA + rsA;
        lB = lB * corrB + rsB;
        #pragma unroll
        for (int t = 0; t < 8; ++t) {
            oacc[t][0] *= corrA; oacc[t][1] *= corrA;
            oacc[t][2] *= corrB; oacc[t][3] *= corrB;
        }
        mA = mnA; mB = mnB;

        // ---- O += P V (split-3) ----
        #pragma unroll
        for (int ks = 0; ks < 4; ++ks) {
            uint32_t pfh[4], pfl[4];
            {
                float h00, l00, h01, l01, h10, l10, h11, l11;
                bsplit(sacc[2 * ks][0], h00, l00); bsplit(sacc[2 * ks][1], h01, l01);
                bsplit(sacc[2 * ks][2], h10, l10); bsplit(sacc[2 * ks][3], h11, l11);
                pfh[0] = packbf(h00, h01); pfl[0] = packbf(l00, l01);
                pfh[1] = packbf(h10, h11); pfl[1] = packbf(l10, l11);
                bsplit(sacc[2 * ks + 1][0], h00, l00); bsplit(sacc[2 * ks + 1][1], h01, l01);
                bsplit(sacc[2 * ks + 1][2], h10, l10); bsplit(sacc[2 * ks + 1][3], h11, l11);
                pfh[2] = packbf(h00, h01); pfl[2] = packbf(l00, l01);
                pfh[3] = packbf(h10, h11); pfl[3] = packbf(l10, l11);
            }
            #pragma unroll
            for (int ep = 0; ep < 4; ++ep) {
                uint32_t row = ks * 16 + vb_row;
                uint32_t eo  = ep * 16 + vb_eoff;
                uint32_t v0, v1, v2, v3, w0, w1, w2, w3;
                LDSM_X4_T(v0, v1, v2, v3, Vh_b + row * 144 + eo * 2);
                LDSM_X4_T(w0, w1, w2, w3, Vl_b + row * 144 + eo * 2);
                mma16816(oacc[2 * ep],     pfh[0], pfh[1], pfh[2], pfh[3], v0, v1);
                mma16816(oacc[2 * ep],     pfh[0], pfh[1], pfh[2], pfh[3], w0, w1);
                mma16816(oacc[2 * ep],     pfl[0], pfl[1], pfl[2], pfl[3], v0, v1);
                mma16816(oacc[2 * ep + 1], pfh[0], pfh[1], pfh[2], pfh[3], v2, v3);
                mma16816(oacc[2 * ep + 1], pfh[0], pfh[1], pfh[2], pfh[3], w2, w3);
                mma16816(oacc[2 * ep + 1], pfl[0], pfl[1], pfl[2], pfl[3], v2, v3);
            }
        }
        __syncthreads();
    }

    // ---- finalize: write concat as bf16 hi/lo ----
    const float invA = 1.0f / lA;
    const float invB = 1.0f / lB;
    const int b = bh >> 4, h = bh & 15;
    const int e0 = 2 * (lane & 3);
    size_t baseA = ((size_t)b * S_ + rA_g) * D_ + h * DH_;
    size_t baseB = ((size_t)b * S_ + rA_g + 8) * D_ + h * DH_;
    #pragma unroll
    for (int t = 0; t < 8; ++t) {
        int e = 8 * t + e0;
        float a0 = oacc[t][0] * invA, a1 = oacc[t][1] * invA;
        float b0v = oacc[t][2] * invB, b1v = oacc[t][3] * invB;
        float h0, l0, h1, l1;
        bsplit(a0, h0, l0); bsplit(a1, h1, l1);
        *(uint32_t*)(g_ch + baseA + e) = packbf(h0, h1);
        *(uint32_t*)(g_cl + baseA + e) = packbf(l0, l1);
        bsplit(b0v, h0, l0); bsplit(b1v, h1, l1);
        *(uint32_t*)(g_ch + baseB + e) = packbf(h0, h1);
        *(uint32_t*)(g_cl + baseB + e) = packbf(l0, l1);
    }
}

// ============================================================
extern "C" void kernel_launch(void* const* d_in, const int* in_sizes, int n_in,
                              void* d_out, int out_size)
{
    const float* x  = (const float*)d_in[0];
    const float* Wq = (const float*)d_in[1];
    const float* Wk = (const float*)d_in[2];
    const float* Wv = (const float*)d_in[3];
    const float* Wo = (const float*)d_in[4];
    const float* bo = (const float*)d_in[5];
    float* out = (float*)d_out;

    cudaFuncSetAttribute(qkv_mma_kernel, cudaFuncAttributeMaxDynamicSharedMemorySize, GEMM_SMEM);
    cudaFuncSetAttribute(out_proj_mma_kernel, cudaFuncAttributeMaxDynamicSharedMemorySize, GEMM_SMEM);
    cudaFuncSetAttribute(attn_mma_kernel, cudaFuncAttributeMaxDynamicSharedMemorySize, ATTN_SMEM);

    conv_x_kernel<<<C_ELEMS / 4 / 256, 256>>>(x);
    conv_w_kernel<<<dim3(D_ / 64, H_, 3), 256>>>(Wq, Wk, Wv);
    conv_wo_kernel<<<dim3(D_ / 64, D_ / 64), 256>>>(Wo);
    qkv_mma_kernel<<<dim3(MROWS / 128, H_ / 2, 3), 256, GEMM_SMEM>>>();
    attn_mma_kernel<<<dim3(S_ / 128, B_ * H_), 256, ATTN_SMEM>>>();
    out_proj_mma_kernel<<<dim3(MROWS / 128, D_ / 128), 256, GEMM_SMEM>>>(bo, out);
}